// round 14
// baseline (speedup 1.0000x reference)
#include <cuda_runtime.h>
#include <cuda_fp16.h>
#include <cstdint>

#define BB 4
#define SS 4096
#define DD 1024
#define MTOT (BB*SS)

#define BM 128
#define BN 128
#define BK 32
#define TILE_B 8192                 // 128 rows x 64 bytes, swizzled
#define STAGE_B (2*TILE_B)          // 16 KB
#define SMEM_BYTES  49152           // 3-stage -> 2 CTAs/SM (128 thr)
#define SMEM_BYTES6 98304           // 6-stage (k_M only)
#define NTHR 128                    // 4 warps: 2x2 of 64x64

// PV variant: CTA 128 x 256, 8 warps (2x4 of 64x64), 256 thr
#define PV_BN 256
#define PV_TILE_B2 16384            // 256 rows x 64B
#define PV_STAGE (TILE_B + PV_TILE_B2)   // 24 KB
#define PV_NST 4
#define PV_SMEM (PV_NST*PV_STAGE)   // 96 KB
#define PV_NTHR 256

// ---------------- device scratch ----------------
__device__ __half g_xh [(size_t)MTOT*DD];
__device__ __half g_Qh [(size_t)DD*DD];
__device__ __half g_Kh [(size_t)DD*DD];
__device__ __half g_Wtv[(size_t)DD*DD];     // V^T: [n][k]
__device__ __half g_Mt [(size_t)DD*DD];     // (K Q^T)
__device__ __half g_Yh [(size_t)MTOT*DD];   // y = x @ (Q K^T)
__device__ __half g_Vxh[(size_t)MTOT*DD];
__device__ __half g_Vth[(size_t)MTOT*DD];   // Vx^T: [b][d][s]
__device__ __half g_Sh [(size_t)BB*SS*SS];  // scaled logits, fp16
__device__ __half g_Ph [(size_t)BB*SS*SS];

// ---------------- asm helpers ----------------
__device__ __forceinline__ uint32_t smem_u32(const void* p){
    uint32_t a;
    asm("{ .reg .u64 t; cvta.to.shared.u64 t, %1; cvt.u32.u64 %0, t; }" : "=r"(a) : "l"(p));
    return a;
}
#define CPA(dst, src) asm volatile("cp.async.cg.shared.global [%0], [%1], 16;" :: "r"(dst), "l"(src))
#define CPC()  asm volatile("cp.async.commit_group;")

template<int N> __device__ __forceinline__ void cp_wait();
template<> __device__ __forceinline__ void cp_wait<1>(){ asm volatile("cp.async.wait_group 1;"); }
template<> __device__ __forceinline__ void cp_wait<2>(){ asm volatile("cp.async.wait_group 2;"); }
template<> __device__ __forceinline__ void cp_wait<4>(){ asm volatile("cp.async.wait_group 4;"); }

#define LDSM4(r0,r1,r2,r3,addr) \
    asm volatile("ldmatrix.sync.aligned.m8n8.x4.shared.b16 {%0,%1,%2,%3}, [%4];" \
        : "=r"(r0), "=r"(r1), "=r"(r2), "=r"(r3) : "r"(addr))

#define MMA(d, a, b) asm volatile( \
    "mma.sync.aligned.m16n8k16.row.col.f32.f16.f16.f32 " \
    "{%0,%1,%2,%3}, {%4,%5,%6,%7}, {%8,%9}, {%0,%1,%2,%3};" \
    : "+f"((d)[0]), "+f"((d)[1]), "+f"((d)[2]), "+f"((d)[3]) \
    : "r"((a)[0]), "r"((a)[1]), "r"((a)[2]), "r"((a)[3]), "r"((b)[0]), "r"((b)[1]))

__device__ __forceinline__ uint32_t swz(uint32_t r, uint32_t c){
    return r*64u + ((c ^ (r & 3u)) * 16u);
}

// ---------------- generic 128x128 path (4 warps, 128 thr) ----------------
__device__ __forceinline__ void load_stage(uint32_t sm,
    const __half* A, size_t lda, int r0a,
    const __half* B, size_t ldb, int r0b,
    int k0, int tid)
{
#pragma unroll
    for (int i = 0; i < 4; i++){
        int id = tid + i*NTHR;                // 0..511
        uint32_t r = (uint32_t)(id >> 2), c = (uint32_t)(id & 3);
        uint32_t so = swz(r, c);
        size_t goa = (size_t)(r0a + (int)r)*lda + k0 + c*8;
        size_t gob = (size_t)(r0b + (int)r)*ldb + k0 + c*8;
        CPA(sm + so,          A + goa);
        CPA(sm + TILE_B + so, B + gob);
    }
}

__device__ __forceinline__ void compute_warp64(uint32_t aA, uint32_t aB,
                                               int lane, int wm, int wn,
                                               float acc[4][8][4])
{
    const int ar = lane & 15;
    const int ac = lane >> 4;
    const int br = (lane & 7) | ((lane >> 4) << 3);
    const int bc = (lane >> 3) & 1;
#pragma unroll
    for (int ks = 0; ks < 2; ks++){
        uint32_t a[4][4], bh[8][2];
#pragma unroll
        for (int mi = 0; mi < 4; mi++){
            uint32_t r = (uint32_t)(wm*64 + mi*16 + ar);
            LDSM4(a[mi][0], a[mi][1], a[mi][2], a[mi][3], aA + swz(r, (uint32_t)(ks*2 + ac)));
        }
#pragma unroll
        for (int np = 0; np < 4; np++){
            uint32_t r = (uint32_t)(wn*64 + np*16 + br);
            LDSM4(bh[2*np][0], bh[2*np][1], bh[2*np+1][0], bh[2*np+1][1], aB + swz(r, (uint32_t)(ks*2 + bc)));
        }
#pragma unroll
        for (int mi = 0; mi < 4; mi++)
#pragma unroll
            for (int ni = 0; ni < 8; ni++)
                MMA(acc[mi][ni], a[mi], bh[ni]);
    }
}

template<int NST>
__device__ __forceinline__ void gemm_run(uint32_t sm, int tid,
    const __half* A, size_t lda, int r0a,
    const __half* B, size_t ldb, int r0b,
    int ktiles, float acc[4][8][4])
{
    const int lane = tid & 31, wid = tid >> 5;
    const int wm = wid & 1, wn = wid >> 1;
    const int kend = ktiles * BK;

#pragma unroll
    for (int s = 0; s < NST - 1; s++){
        int k = min(s * BK, kend - BK);
        load_stage(sm + s*STAGE_B, A, lda, r0a, B, ldb, r0b, k, tid);
        CPC();
    }
    int buf = 0, nxt = NST - 1;
    for (int kt = 0; kt < ktiles; kt++){
        cp_wait<NST-2>();
        __syncthreads();
        {
            int k = min((kt + NST - 1) * BK, kend - BK);
            load_stage(sm + nxt*STAGE_B, A, lda, r0a, B, ldb, r0b, k, tid);
            CPC();
        }
        compute_warp64(sm + buf*STAGE_B, sm + buf*STAGE_B + TILE_B, lane, wm, wn, acc);
        buf = (buf + 1 == NST) ? 0 : buf + 1;
        nxt = (nxt + 1 == NST) ? 0 : nxt + 1;
    }
}

// ---------------- PV path: 128x256 CTA (8 warps, 256 thr) ----------------
__device__ __forceinline__ void pv_load_stage(uint32_t sm,
    const __half* A, size_t lda, int r0a,
    const __half* B, size_t ldb, int r0b,
    int k0, int tid)
{
#pragma unroll
    for (int i = 0; i < 2; i++){
        int id = tid + i*PV_NTHR;             // 0..511 (A: 128 rows x 4 chunks)
        uint32_t r = (uint32_t)(id >> 2), c = (uint32_t)(id & 3);
        size_t goa = (size_t)(r0a + (int)r)*lda + k0 + c*8;
        CPA(sm + swz(r, c), A + goa);
    }
    const uint32_t bb = sm + TILE_B;
#pragma unroll
    for (int i = 0; i < 4; i++){
        int id = tid + i*PV_NTHR;             // 0..1023 (B: 256 rows x 4 chunks)
        uint32_t r = (uint32_t)(id >> 2), c = (uint32_t)(id & 3);
        size_t gob = (size_t)(r0b + (int)r)*ldb + k0 + c*8;
        CPA(bb + swz(r, c), B + gob);
    }
}

__device__ __forceinline__ void pv_gemm_run(uint32_t sm, int tid,
    const __half* A, size_t lda, int r0a,
    const __half* B, size_t ldb, int r0b,
    int ktiles, float acc[4][8][4])
{
    const int lane = tid & 31, wid = tid >> 5;
    const int wm = wid & 1, wn = wid >> 1;    // wn 0..3
    const int kend = ktiles * BK;

#pragma unroll
    for (int s = 0; s < PV_NST - 1; s++){
        int k = min(s * BK, kend - BK);
        pv_load_stage(sm + s*PV_STAGE, A, lda, r0a, B, ldb, r0b, k, tid);
        CPC();
    }
    int buf = 0, nxt = PV_NST - 1;
    for (int kt = 0; kt < ktiles; kt++){
        cp_wait<PV_NST-2>();
        __syncthreads();
        {
            int k = min((kt + PV_NST - 1) * BK, kend - BK);
            pv_load_stage(sm + nxt*PV_STAGE, A, lda, r0a, B, ldb, r0b, k, tid);
            CPC();
        }
        compute_warp64(sm + buf*PV_STAGE, sm + buf*PV_STAGE + TILE_B, lane, wm, wn, acc);
        buf = (buf + 1 == PV_NST) ? 0 : buf + 1;
        nxt = (nxt + 1 == PV_NST) ? 0 : nxt + 1;
    }
}

// ---------------- kernel 1: x -> fp16 ----------------
__global__ void k_half_x(const float* __restrict__ x){
    size_t i = ((size_t)blockIdx.x * 256 + threadIdx.x) * 4;
    float4 v = *reinterpret_cast<const float4*>(x + i);
    __half2 h01{__float2half(v.x), __float2half(v.y)};
    __half2 h23{__float2half(v.z), __float2half(v.w)};
    *reinterpret_cast<__half2*>(g_xh + i)     = h01;
    *reinterpret_cast<__half2*>(g_xh + i + 2) = h23;
}

// ---------------- kernel 2a: Q,K weights -> fp16 ----------------
__global__ void k_half_w(const float* __restrict__ Wq,
                         const float* __restrict__ Wk){
    const float* W = blockIdx.y ? Wk : Wq;
    __half* H      = blockIdx.y ? g_Kh : g_Qh;
    size_t i = ((size_t)blockIdx.x * 256 + threadIdx.x) * 4;
    float4 v = *reinterpret_cast<const float4*>(W + i);
    __half2 h01{__float2half(v.x), __float2half(v.y)};
    __half2 h23{__float2half(v.z), __float2half(v.w)};
    *reinterpret_cast<__half2*>(H + i)     = h01;
    *reinterpret_cast<__half2*>(H + i + 2) = h23;
}

// ---------------- kernel 2b: transpose V -> fp16 ----------------
__global__ void k_wtrans(const float* __restrict__ Wv){
    __shared__ float t[32][33];
    int tx = threadIdx.x, ty = threadIdx.y;
    int kb = blockIdx.y * 32, nb = blockIdx.x * 32;
#pragma unroll
    for (int j = 0; j < 4; j++)
        t[ty + j*8][tx] = Wv[(size_t)(kb + ty + j*8)*DD + nb + tx];
    __syncthreads();
#pragma unroll
    for (int j = 0; j < 4; j++){
        int n = nb + ty + j*8, k = kb + tx;
        g_Wtv[(size_t)n*DD + k] = __float2half(t[tx][ty + j*8]);
    }
}

// ---------------- kernel 3: Mt = K @ Q^T ----------------
__global__ void __launch_bounds__(NTHR, 1) k_M(){
    extern __shared__ __align__(128) char smem[];
    uint32_t sm = smem_u32(smem);
    const int tid = threadIdx.x;
    const int m0 = blockIdx.y*BM, n0 = blockIdx.x*BN;
    float acc[4][8][4] = {};
    gemm_run<6>(sm, tid, g_Kh, DD, m0, g_Qh, DD, n0, DD/BK, acc);
    const int lane = tid & 31, wid = tid >> 5, wm = wid & 1, wn = wid >> 1;
    const int r = lane >> 2, c = (lane & 3) * 2;
#pragma unroll
    for (int mi = 0; mi < 4; mi++)
#pragma unroll
        for (int ni = 0; ni < 8; ni++){
            int row = m0 + wm*64 + mi*16 + r;
            int col = n0 + wn*64 + ni*8 + c;
#pragma unroll
            for (int hrow = 0; hrow < 2; hrow++){
                __half2 hp{__float2half(acc[mi][ni][hrow*2+0]),
                           __float2half(acc[mi][ni][hrow*2+1])};
                *reinterpret_cast<__half2*>(g_Mt + (size_t)(row + hrow*8)*DD + col) = hp;
            }
        }
}

// ---------------- kernel 4: V projection -> fp16 ----------------
__global__ void __launch_bounds__(NTHR, 2) k_proj_v(){
    extern __shared__ __align__(128) char smem[];
    uint32_t sm = smem_u32(smem);
    const int tid = threadIdx.x;
    const int m0 = blockIdx.y*BM, n0 = blockIdx.x*BN;
    float acc[4][8][4] = {};
    gemm_run<3>(sm, tid, g_xh, DD, m0, g_Wtv, DD, n0, DD/BK, acc);
    const int lane = tid & 31, wid = tid >> 5, wm = wid & 1, wn = wid >> 1;
    const int r = lane >> 2, c = (lane & 3) * 2;
#pragma unroll
    for (int mi = 0; mi < 4; mi++)
#pragma unroll
        for (int ni = 0; ni < 8; ni++){
            int row = m0 + wm*64 + mi*16 + r;
            int col = n0 + wn*64 + ni*8 + c;
#pragma unroll
            for (int hrow = 0; hrow < 2; hrow++){
                size_t o = (size_t)(row + hrow*8)*DD + col;
                __half2 hp{__float2half(acc[mi][ni][hrow*2+0]),
                           __float2half(acc[mi][ni][hrow*2+1])};
                *reinterpret_cast<__half2*>(g_Vxh + o) = hp;
            }
        }
}

// ---------------- kernel 5: y = x @ M ----------------
__global__ void __launch_bounds__(NTHR, 2) k_y(){
    extern __shared__ __align__(128) char smem[];
    uint32_t sm = smem_u32(smem);
    const int tid = threadIdx.x;
    const int m0 = blockIdx.y*BM, n0 = blockIdx.x*BN;
    float acc[4][8][4] = {};
    gemm_run<3>(sm, tid, g_xh, DD, m0, g_Mt, DD, n0, DD/BK, acc);
    const int lane = tid & 31, wid = tid >> 5, wm = wid & 1, wn = wid >> 1;
    const int r = lane >> 2, c = (lane & 3) * 2;
#pragma unroll
    for (int mi = 0; mi < 4; mi++)
#pragma unroll
        for (int ni = 0; ni < 8; ni++){
            int row = m0 + wm*64 + mi*16 + r;
            int col = n0 + wn*64 + ni*8 + c;
#pragma unroll
            for (int hrow = 0; hrow < 2; hrow++){
                __half2 hp{__float2half(acc[mi][ni][hrow*2+0]),
                           __float2half(acc[mi][ni][hrow*2+1])};
                *reinterpret_cast<__half2*>(g_Yh + (size_t)(row + hrow*8)*DD + col) = hp;
            }
        }
}

// ---------------- kernel 6: transpose Vx ----------------
__global__ void k_vtrans(){
    const int b = blockIdx.z;
    const __half* Vx = g_Vxh + (size_t)b*SS*DD;
    __half* H = g_Vth + (size_t)b*DD*SS;
    __shared__ float t[32][33];
    int tx = threadIdx.x, ty = threadIdx.y;
    int s0 = blockIdx.y * 32, d0 = blockIdx.x * 32;
#pragma unroll
    for (int j = 0; j < 4; j++)
        t[ty + j*8][tx] = __half2float(Vx[(size_t)(s0 + ty + j*8)*DD + d0 + tx]);
    __syncthreads();
#pragma unroll
    for (int j = 0; j < 4; j++){
        int d = d0 + ty + j*8, s = s0 + tx;
        H[(size_t)d*SS + s] = __float2half(t[tx][ty + j*8]);
    }
}

// ---------------- kernel 7: scores = y @ x^T (lower-tri, fp16 out) ----------
__global__ void __launch_bounds__(NTHR, 2) k_scores(){
    const int kt = blockIdx.x, qt = blockIdx.y, b = blockIdx.z;
    if (kt > qt) return;
    extern __shared__ __align__(128) char smem[];
    uint32_t sm = smem_u32(smem);
    const int tid = threadIdx.x;
    float acc[4][8][4] = {};
    gemm_run<3>(sm, tid,
                g_Yh + (size_t)b*SS*DD, DD, qt*BM,
                g_xh + (size_t)b*SS*DD, DD, kt*BN, DD/BK, acc);
    const int lane = tid & 31, wid = tid >> 5, wm = wid & 1, wn = wid >> 1;
    const int r = lane >> 2, c = (lane & 3) * 2;
    __half* Sp = g_Sh + (size_t)b*SS*SS;
#pragma unroll
    for (int mi = 0; mi < 4; mi++)
#pragma unroll
        for (int ni = 0; ni < 8; ni++){
            int row = qt*BM + wm*64 + mi*16 + r;
            int col = kt*BN + wn*64 + ni*8 + c;
#pragma unroll
            for (int hrow = 0; hrow < 2; hrow++){
                size_t o = (size_t)(row + hrow*8)*SS + col;
                __half2 hp{__float2half(acc[mi][ni][hrow*2+0]*0.03125f),
                           __float2half(acc[mi][ni][hrow*2+1]*0.03125f)};
                *reinterpret_cast<__half2*>(Sp + o) = hp;
            }
        }
}

// ---------------- kernel 8: softmax (fp16 in) -> fp16 probs + pad ----------
__global__ void k_softmax(){
    const int q = blockIdx.x;
    const int b = blockIdx.y;
    const __half* row = g_Sh + (size_t)b*SS*SS + (size_t)q*SS;
    __half* Ph = g_Ph + (size_t)b*SS*SS + (size_t)q*SS;
    const int len = q + 1;

    __shared__ float buf[SS];
    __shared__ float red[256];
    const int tid = threadIdx.x;

    float mx = -1e30f;
    for (int i = tid; i < len; i += 256){
        float v = __half2float(row[i]);
        buf[i] = v;
        mx = fmaxf(mx, v);
    }
    red[tid] = mx;
    __syncthreads();
    for (int s = 128; s > 0; s >>= 1){
        if (tid < s) red[tid] = fmaxf(red[tid], red[tid + s]);
        __syncthreads();
    }
    mx = red[0];
    __syncthreads();

    float sum = 0.f;
    for (int i = tid; i < len; i += 256){
        float e = __expf(buf[i] - mx);
        buf[i] = e;
        sum += e;
    }
    red[tid] = sum;
    __syncthreads();
    for (int s = 128; s > 0; s >>= 1){
        if (tid < s) red[tid] += red[tid + s];
        __syncthreads();
    }
    const float inv = 1.0f / red[0];
    __syncthreads();

    for (int i = tid; i < len; i += 256)
        Ph[i] = __float2half(buf[i] * inv);
    const int bound = ((q >> 7) + 1) << 7;
    const __half z = __float2half(0.f);
    for (int i = len + tid; i < bound; i += 256) Ph[i] = z;
}

// ---------------- kernel 9: O = P @ V (128x256 tiles; longest-first) --------
__global__ void __launch_bounds__(PV_NTHR, 1) k_pv(float* __restrict__ Out){
    const int dt = blockIdx.x, b = blockIdx.z;
    const int qt = (int)gridDim.y - 1 - (int)blockIdx.y;
    extern __shared__ __align__(128) char smem[];
    uint32_t sm = smem_u32(smem);
    const int tid = threadIdx.x;
    float acc[4][8][4] = {};
    const int ktiles = (qt + 1) * (BM / BK);
    pv_gemm_run(sm, tid,
                g_Ph  + (size_t)b*SS*SS, SS, qt*BM,
                g_Vth + (size_t)b*DD*SS, SS, dt*PV_BN, ktiles, acc);
    const int lane = tid & 31, wid = tid >> 5, wm = wid & 1, wn = wid >> 1;
    const int r = lane >> 2, c = (lane & 3) * 2;
#pragma unroll
    for (int mi = 0; mi < 4; mi++)
#pragma unroll
        for (int ni = 0; ni < 8; ni++){
            int row = qt*BM + wm*64 + mi*16 + r;
            int col = dt*PV_BN + wn*64 + ni*8 + c;
#pragma unroll
            for (int hrow = 0; hrow < 2; hrow++){
                size_t o = ((size_t)b*SS + row + hrow*8)*DD + col;
                *reinterpret_cast<float2*>(Out + o) =
                    make_float2(acc[mi][ni][hrow*2+0], acc[mi][ni][hrow*2+1]);
            }
        }
}

// ---------------- host ----------------
extern "C" void kernel_launch(void* const* d_in, const int* in_sizes, int n_in,
                              void* d_out, int out_size) {
    const float* x  = (const float*)d_in[0];
    const float* Q  = (const float*)d_in[1];
    const float* K  = (const float*)d_in[2];
    const float* V  = (const float*)d_in[3];
    float* out = (float*)d_out;

    cudaFuncSetAttribute(k_M,      cudaFuncAttributeMaxDynamicSharedMemorySize, SMEM_BYTES6);
    cudaFuncSetAttribute(k_proj_v, cudaFuncAttributeMaxDynamicSharedMemorySize, SMEM_BYTES);
    cudaFuncSetAttribute(k_y,      cudaFuncAttributeMaxDynamicSharedMemorySize, SMEM_BYTES);
    cudaFuncSetAttribute(k_scores, cudaFuncAttributeMaxDynamicSharedMemorySize, SMEM_BYTES);
    cudaFuncSetAttribute(k_pv,     cudaFuncAttributeMaxDynamicSharedMemorySize, PV_SMEM);

    k_half_x<<<(unsigned)((size_t)MTOT*DD/1024), 256>>>(x);
    k_half_w<<<dim3(DD*DD/1024, 2), 256>>>(Q, K);
    k_wtrans<<<dim3(DD/32, DD/32), dim3(32, 8)>>>(V);
    k_M<<<dim3(DD/BN, DD/BM), NTHR, SMEM_BYTES6>>>();
    k_proj_v<<<dim3(DD/BN, MTOT/BM), NTHR, SMEM_BYTES>>>();
    k_y<<<dim3(DD/BN, MTOT/BM), NTHR, SMEM_BYTES>>>();
    k_vtrans<<<dim3(DD/32, SS/32, BB), dim3(32, 8)>>>();
    k_scores<<<dim3(SS/BN, SS/BM, BB), NTHR, SMEM_BYTES>>>();
    k_softmax<<<dim3(SS, BB), 256>>>();
    k_pv<<<dim3(DD/PV_BN, SS/BM, BB), PV_NTHR, PV_SMEM>>>(out);
}

// round 15
// speedup vs baseline: 1.0578x; 1.0578x over previous
#include <cuda_runtime.h>
#include <cuda_fp16.h>
#include <cstdint>

#define BB 4
#define SS 4096
#define DD 1024
#define MTOT (BB*SS)

#define BM 128
#define BN 128
#define BK 32
#define TILE_B 8192                 // 128 rows x 64 bytes, swizzled
#define STAGE_B (2*TILE_B)          // 16 KB
#define SMEM_BYTES  49152           // 3-stage -> 2 CTAs/SM (128 thr)
#define SMEM_BYTES6 98304           // 6-stage (k_M only)
#define NTHR 128                    // 4 warps: 2x2 of 64x64

// ---------------- device scratch ----------------
__device__ __half g_xh [(size_t)MTOT*DD];
__device__ __half g_Qh [(size_t)DD*DD];
__device__ __half g_Kh [(size_t)DD*DD];
__device__ __half g_Wtv[(size_t)DD*DD];     // V^T: [n][k]
__device__ __half g_Mt [(size_t)DD*DD];     // (K Q^T)
__device__ __half g_Yh [(size_t)MTOT*DD];   // y = x @ (Q K^T)
__device__ __half g_Vxh[(size_t)MTOT*DD];
__device__ __half g_Vth[(size_t)MTOT*DD];   // Vx^T: [b][d][s]
__device__ __half g_Sh [(size_t)BB*SS*SS];  // scaled logits, fp16
__device__ __half g_Ph [(size_t)BB*SS*SS];

// ---------------- asm helpers ----------------
__device__ __forceinline__ uint32_t smem_u32(const void* p){
    uint32_t a;
    asm("{ .reg .u64 t; cvta.to.shared.u64 t, %1; cvt.u32.u64 %0, t; }" : "=r"(a) : "l"(p));
    return a;
}
#define CPA(dst, src) asm volatile("cp.async.cg.shared.global [%0], [%1], 16;" :: "r"(dst), "l"(src))
#define CPC()  asm volatile("cp.async.commit_group;")

template<int N> __device__ __forceinline__ void cp_wait();
template<> __device__ __forceinline__ void cp_wait<1>(){ asm volatile("cp.async.wait_group 1;"); }
template<> __device__ __forceinline__ void cp_wait<4>(){ asm volatile("cp.async.wait_group 4;"); }

#define LDSM4(r0,r1,r2,r3,addr) \
    asm volatile("ldmatrix.sync.aligned.m8n8.x4.shared.b16 {%0,%1,%2,%3}, [%4];" \
        : "=r"(r0), "=r"(r1), "=r"(r2), "=r"(r3) : "r"(addr))

#define MMA(d, a, b) asm volatile( \
    "mma.sync.aligned.m16n8k16.row.col.f32.f16.f16.f32 " \
    "{%0,%1,%2,%3}, {%4,%5,%6,%7}, {%8,%9}, {%0,%1,%2,%3};" \
    : "+f"((d)[0]), "+f"((d)[1]), "+f"((d)[2]), "+f"((d)[3]) \
    : "r"((a)[0]), "r"((a)[1]), "r"((a)[2]), "r"((a)[3]), "r"((b)[0]), "r"((b)[1]))

__device__ __forceinline__ uint32_t swz(uint32_t r, uint32_t c){
    return r*64u + ((c ^ (r & 3u)) * 16u);
}

// ---------------- stage load (cp.async, swizzled): A, B — 128 threads -------
__device__ __forceinline__ void load_stage(uint32_t sm,
    const __half* A, size_t lda, int r0a,
    const __half* B, size_t ldb, int r0b,
    int k0, int tid)
{
#pragma unroll
    for (int i = 0; i < 4; i++){
        int id = tid + i*NTHR;                // 0..511
        uint32_t r = (uint32_t)(id >> 2), c = (uint32_t)(id & 3);
        uint32_t so = swz(r, c);
        size_t goa = (size_t)(r0a + (int)r)*lda + k0 + c*8;
        size_t gob = (size_t)(r0b + (int)r)*ldb + k0 + c*8;
        CPA(sm + so,          A + goa);
        CPA(sm + TILE_B + so, B + gob);
    }
}

// ---------------- stage compute: warp tile 64x64, 1-pass ----------------
__device__ __forceinline__ void compute_stage(uint32_t sm, int lane, int wm, int wn,
                                              float acc[4][8][4])
{
    const uint32_t aA = sm;
    const uint32_t aB = sm + TILE_B;
    const int ar = lane & 15;
    const int ac = lane >> 4;
    const int br = (lane & 7) | ((lane >> 4) << 3);
    const int bc = (lane >> 3) & 1;
#pragma unroll
    for (int ks = 0; ks < 2; ks++){
        uint32_t a[4][4], bh[8][2];
#pragma unroll
        for (int mi = 0; mi < 4; mi++){
            uint32_t r = (uint32_t)(wm*64 + mi*16 + ar);
            LDSM4(a[mi][0], a[mi][1], a[mi][2], a[mi][3], aA + swz(r, (uint32_t)(ks*2 + ac)));
        }
#pragma unroll
        for (int np = 0; np < 4; np++){
            uint32_t r = (uint32_t)(wn*64 + np*16 + br);
            LDSM4(bh[2*np][0], bh[2*np][1], bh[2*np+1][0], bh[2*np+1][1], aB + swz(r, (uint32_t)(ks*2 + bc)));
        }
#pragma unroll
        for (int mi = 0; mi < 4; mi++)
#pragma unroll
            for (int ni = 0; ni < 8; ni++)
                MMA(acc[mi][ni], a[mi], bh[ni]);
    }
}

// ---------------- GEMM mainloop (NST-stage pipeline, 1 sync/iter) ----------------
template<int NST>
__device__ __forceinline__ void gemm_run(uint32_t sm, int tid,
    const __half* A, size_t lda, int r0a,
    const __half* B, size_t ldb, int r0b,
    int ktiles, float acc[4][8][4])
{
    const int lane = tid & 31, wid = tid >> 5;
    const int wm = wid & 1, wn = wid >> 1;
    const int kend = ktiles * BK;

#pragma unroll
    for (int s = 0; s < NST - 1; s++){
        int k = min(s * BK, kend - BK);
        load_stage(sm + s*STAGE_B, A, lda, r0a, B, ldb, r0b, k, tid);
        CPC();
    }
    int buf = 0, nxt = NST - 1;
    for (int kt = 0; kt < ktiles; kt++){
        cp_wait<NST-2>();
        __syncthreads();
        {
            int k = min((kt + NST - 1) * BK, kend - BK);
            load_stage(sm + nxt*STAGE_B, A, lda, r0a, B, ldb, r0b, k, tid);
            CPC();
        }
        compute_stage(sm + buf*STAGE_B, lane, wm, wn, acc);
        buf = (buf + 1 == NST) ? 0 : buf + 1;
        nxt = (nxt + 1 == NST) ? 0 : nxt + 1;
    }
}

// ---------------- kernel 1: x -> fp16 ----------------
__global__ void k_half_x(const float* __restrict__ x){
    size_t i = ((size_t)blockIdx.x * 256 + threadIdx.x) * 4;
    float4 v = *reinterpret_cast<const float4*>(x + i);
    __half2 h01{__float2half(v.x), __float2half(v.y)};
    __half2 h23{__float2half(v.z), __float2half(v.w)};
    *reinterpret_cast<__half2*>(g_xh + i)     = h01;
    *reinterpret_cast<__half2*>(g_xh + i + 2) = h23;
}

// ---------------- kernel 2a: Q,K weights -> fp16 ----------------
__global__ void k_half_w(const float* __restrict__ Wq,
                         const float* __restrict__ Wk){
    const float* W = blockIdx.y ? Wk : Wq;
    __half* H      = blockIdx.y ? g_Kh : g_Qh;
    size_t i = ((size_t)blockIdx.x * 256 + threadIdx.x) * 4;
    float4 v = *reinterpret_cast<const float4*>(W + i);
    __half2 h01{__float2half(v.x), __float2half(v.y)};
    __half2 h23{__float2half(v.z), __float2half(v.w)};
    *reinterpret_cast<__half2*>(H + i)     = h01;
    *reinterpret_cast<__half2*>(H + i + 2) = h23;
}

// ---------------- kernel 2b: transpose V -> fp16 ----------------
__global__ void k_wtrans(const float* __restrict__ Wv){
    __shared__ float t[32][33];
    int tx = threadIdx.x, ty = threadIdx.y;
    int kb = blockIdx.y * 32, nb = blockIdx.x * 32;
#pragma unroll
    for (int j = 0; j < 4; j++)
        t[ty + j*8][tx] = Wv[(size_t)(kb + ty + j*8)*DD + nb + tx];
    __syncthreads();
#pragma unroll
    for (int j = 0; j < 4; j++){
        int n = nb + ty + j*8, k = kb + tx;
        g_Wtv[(size_t)n*DD + k] = __float2half(t[tx][ty + j*8]);
    }
}

// ---------------- kernel 3: Mt = K @ Q^T ----------------
__global__ void __launch_bounds__(NTHR, 1) k_M(){
    extern __shared__ __align__(128) char smem[];
    uint32_t sm = smem_u32(smem);
    const int tid = threadIdx.x;
    const int m0 = blockIdx.y*BM, n0 = blockIdx.x*BN;
    float acc[4][8][4] = {};
    gemm_run<6>(sm, tid, g_Kh, DD, m0, g_Qh, DD, n0, DD/BK, acc);
    const int lane = tid & 31, wid = tid >> 5, wm = wid & 1, wn = wid >> 1;
    const int r = lane >> 2, c = (lane & 3) * 2;
#pragma unroll
    for (int mi = 0; mi < 4; mi++)
#pragma unroll
        for (int ni = 0; ni < 8; ni++){
            int row = m0 + wm*64 + mi*16 + r;
            int col = n0 + wn*64 + ni*8 + c;
#pragma unroll
            for (int hrow = 0; hrow < 2; hrow++){
                __half2 hp{__float2half(acc[mi][ni][hrow*2+0]),
                           __float2half(acc[mi][ni][hrow*2+1])};
                *reinterpret_cast<__half2*>(g_Mt + (size_t)(row + hrow*8)*DD + col) = hp;
            }
        }
}

// ---------------- kernel 4: V projection -> fp16 ----------------
__global__ void __launch_bounds__(NTHR, 2) k_proj_v(){
    extern __shared__ __align__(128) char smem[];
    uint32_t sm = smem_u32(smem);
    const int tid = threadIdx.x;
    const int m0 = blockIdx.y*BM, n0 = blockIdx.x*BN;
    float acc[4][8][4] = {};
    gemm_run<3>(sm, tid, g_xh, DD, m0, g_Wtv, DD, n0, DD/BK, acc);
    const int lane = tid & 31, wid = tid >> 5, wm = wid & 1, wn = wid >> 1;
    const int r = lane >> 2, c = (lane & 3) * 2;
#pragma unroll
    for (int mi = 0; mi < 4; mi++)
#pragma unroll
        for (int ni = 0; ni < 8; ni++){
            int row = m0 + wm*64 + mi*16 + r;
            int col = n0 + wn*64 + ni*8 + c;
#pragma unroll
            for (int hrow = 0; hrow < 2; hrow++){
                size_t o = (size_t)(row + hrow*8)*DD + col;
                __half2 hp{__float2half(acc[mi][ni][hrow*2+0]),
                           __float2half(acc[mi][ni][hrow*2+1])};
                *reinterpret_cast<__half2*>(g_Vxh + o) = hp;
            }
        }
}

// ---------------- kernel 5: y = x @ M ----------------
__global__ void __launch_bounds__(NTHR, 2) k_y(){
    extern __shared__ __align__(128) char smem[];
    uint32_t sm = smem_u32(smem);
    const int tid = threadIdx.x;
    const int m0 = blockIdx.y*BM, n0 = blockIdx.x*BN;
    float acc[4][8][4] = {};
    gemm_run<3>(sm, tid, g_xh, DD, m0, g_Mt, DD, n0, DD/BK, acc);
    const int lane = tid & 31, wid = tid >> 5, wm = wid & 1, wn = wid >> 1;
    const int r = lane >> 2, c = (lane & 3) * 2;
#pragma unroll
    for (int mi = 0; mi < 4; mi++)
#pragma unroll
        for (int ni = 0; ni < 8; ni++){
            int row = m0 + wm*64 + mi*16 + r;
            int col = n0 + wn*64 + ni*8 + c;
#pragma unroll
            for (int hrow = 0; hrow < 2; hrow++){
                __half2 hp{__float2half(acc[mi][ni][hrow*2+0]),
                           __float2half(acc[mi][ni][hrow*2+1])};
                *reinterpret_cast<__half2*>(g_Yh + (size_t)(row + hrow*8)*DD + col) = hp;
            }
        }
}

// ---------------- kernel 6: transpose Vx ----------------
__global__ void k_vtrans(){
    const int b = blockIdx.z;
    const __half* Vx = g_Vxh + (size_t)b*SS*DD;
    __half* H = g_Vth + (size_t)b*DD*SS;
    __shared__ float t[32][33];
    int tx = threadIdx.x, ty = threadIdx.y;
    int s0 = blockIdx.y * 32, d0 = blockIdx.x * 32;
#pragma unroll
    for (int j = 0; j < 4; j++)
        t[ty + j*8][tx] = __half2float(Vx[(size_t)(s0 + ty + j*8)*DD + d0 + tx]);
    __syncthreads();
#pragma unroll
    for (int j = 0; j < 4; j++){
        int d = d0 + ty + j*8, s = s0 + tx;
        H[(size_t)d*SS + s] = __float2half(t[tx][ty + j*8]);
    }
}

// ---------------- kernel 7: scores = y @ x^T (lower-tri, fp16 out) ----------
__global__ void __launch_bounds__(NTHR, 2) k_scores(){
    const int kt = blockIdx.x, qt = blockIdx.y, b = blockIdx.z;
    if (kt > qt) return;
    extern __shared__ __align__(128) char smem[];
    uint32_t sm = smem_u32(smem);
    const int tid = threadIdx.x;
    float acc[4][8][4] = {};
    gemm_run<3>(sm, tid,
                g_Yh + (size_t)b*SS*DD, DD, qt*BM,
                g_xh + (size_t)b*SS*DD, DD, kt*BN, DD/BK, acc);
    const int lane = tid & 31, wid = tid >> 5, wm = wid & 1, wn = wid >> 1;
    const int r = lane >> 2, c = (lane & 3) * 2;
    __half* Sp = g_Sh + (size_t)b*SS*SS;
#pragma unroll
    for (int mi = 0; mi < 4; mi++)
#pragma unroll
        for (int ni = 0; ni < 8; ni++){
            int row = qt*BM + wm*64 + mi*16 + r;
            int col = kt*BN + wn*64 + ni*8 + c;
#pragma unroll
            for (int hrow = 0; hrow < 2; hrow++){
                size_t o = (size_t)(row + hrow*8)*SS + col;
                __half2 hp{__float2half(acc[mi][ni][hrow*2+0]*0.03125f),
                           __float2half(acc[mi][ni][hrow*2+1]*0.03125f)};
                *reinterpret_cast<__half2*>(Sp + o) = hp;
            }
        }
}

// ---------------- kernel 8: softmax (fp16 in) -> fp16 probs + pad ----------
__global__ void k_softmax(){
    const int q = blockIdx.x;
    const int b = blockIdx.y;
    const __half* row = g_Sh + (size_t)b*SS*SS + (size_t)q*SS;
    __half* Ph = g_Ph + (size_t)b*SS*SS + (size_t)q*SS;
    const int len = q + 1;

    __shared__ float buf[SS];
    __shared__ float red[256];
    const int tid = threadIdx.x;

    float mx = -1e30f;
    for (int i = tid; i < len; i += 256){
        float v = __half2float(row[i]);
        buf[i] = v;
        mx = fmaxf(mx, v);
    }
    red[tid] = mx;
    __syncthreads();
    for (int s = 128; s > 0; s >>= 1){
        if (tid < s) red[tid] = fmaxf(red[tid], red[tid + s]);
        __syncthreads();
    }
    mx = red[0];
    __syncthreads();

    float sum = 0.f;
    for (int i = tid; i < len; i += 256){
        float e = __expf(buf[i] - mx);
        buf[i] = e;
        sum += e;
    }
    red[tid] = sum;
    __syncthreads();
    for (int s = 128; s > 0; s >>= 1){
        if (tid < s) red[tid] += red[tid + s];
        __syncthreads();
    }
    const float inv = 1.0f / red[0];
    __syncthreads();

    for (int i = tid; i < len; i += 256)
        Ph[i] = __float2half(buf[i] * inv);
    const int bound = ((q >> 7) + 1) << 7;
    const __half z = __float2half(0.f);
    for (int i = len + tid; i < bound; i += 256) Ph[i] = z;
}

// ---------------- kernel 9: O = P @ V (triangular; longest-first) ----------
__global__ void __launch_bounds__(NTHR, 2) k_pv(float* __restrict__ Out){
    const int dt = blockIdx.x, b = blockIdx.z;
    const int qt = (int)gridDim.y - 1 - (int)blockIdx.y;   // longest first
    extern __shared__ __align__(128) char smem[];
    uint32_t sm = smem_u32(smem);
    const int tid = threadIdx.x;
    float acc[4][8][4] = {};
    const int ktiles = (qt + 1) * (BM / BK);
    gemm_run<3>(sm, tid,
                g_Ph  + (size_t)b*SS*SS, SS, qt*BM,
                g_Vth + (size_t)b*DD*SS, SS, dt*BN, ktiles, acc);
    const int lane = tid & 31, wid = tid >> 5, wm = wid & 1, wn = wid >> 1;
    const int r = lane >> 2, c = (lane & 3) * 2;
#pragma unroll
    for (int mi = 0; mi < 4; mi++)
#pragma unroll
        for (int ni = 0; ni < 8; ni++){
            int row = qt*BM + wm*64 + mi*16 + r;
            int col = dt*BN + wn*64 + ni*8 + c;
#pragma unroll
            for (int hrow = 0; hrow < 2; hrow++){
                size_t o = ((size_t)b*SS + row + hrow*8)*DD + col;
                *reinterpret_cast<float2*>(Out + o) =
                    make_float2(acc[mi][ni][hrow*2+0], acc[mi][ni][hrow*2+1]);
            }
        }
}

// ---------------- host ----------------
extern "C" void kernel_launch(void* const* d_in, const int* in_sizes, int n_in,
                              void* d_out, int out_size) {
    const float* x  = (const float*)d_in[0];
    const float* Q  = (const float*)d_in[1];
    const float* K  = (const float*)d_in[2];
    const float* V  = (const float*)d_in[3];
    float* out = (float*)d_out;

    cudaFuncSetAttribute(k_M,      cudaFuncAttributeMaxDynamicSharedMemorySize, SMEM_BYTES6);
    cudaFuncSetAttribute(k_proj_v, cudaFuncAttributeMaxDynamicSharedMemorySize, SMEM_BYTES);
    cudaFuncSetAttribute(k_y,      cudaFuncAttributeMaxDynamicSharedMemorySize, SMEM_BYTES);
    cudaFuncSetAttribute(k_scores, cudaFuncAttributeMaxDynamicSharedMemorySize, SMEM_BYTES);
    cudaFuncSetAttribute(k_pv,     cudaFuncAttributeMaxDynamicSharedMemorySize, SMEM_BYTES);

    k_half_x<<<(unsigned)((size_t)MTOT*DD/1024), 256>>>(x);
    k_half_w<<<dim3(DD*DD/1024, 2), 256>>>(Q, K);
    k_wtrans<<<dim3(DD/32, DD/32), dim3(32, 8)>>>(V);
    k_M<<<dim3(DD/BN, DD/BM), NTHR, SMEM_BYTES6>>>();
    k_proj_v<<<dim3(DD/BN, MTOT/BM), NTHR, SMEM_BYTES>>>();
    k_y<<<dim3(DD/BN, MTOT/BM), NTHR, SMEM_BYTES>>>();
    k_vtrans<<<dim3(DD/32, SS/32, BB), dim3(32, 8)>>>();
    k_scores<<<dim3(SS/BN, SS/BM, BB), NTHR, SMEM_BYTES>>>();
    k_softmax<<<dim3(SS, BB), 256>>>();
    k_pv<<<dim3(DD/BN, SS/BM, BB), NTHR, SMEM_BYTES>>>(out);
}

// round 16
// speedup vs baseline: 1.1018x; 1.0417x over previous
#include <cuda_runtime.h>
#include <cuda_fp16.h>
#include <cstdint>

#define BB 4
#define SS 4096
#define DD 1024
#define MTOT (BB*SS)

#define BM 128
#define BN 128
#define BK 32
#define TILE_B 8192                 // 128 rows x 64 bytes, swizzled
#define STAGE_B (2*TILE_B)          // 16 KB
#define SMEM_BYTES  49152           // 3-stage -> 2 CTAs/SM (128 thr)
#define SMEM_BYTES6 98304           // 6-stage (k_M only)
#define NTHR 128                    // 4 warps: 2x2 of 64x64

// ---------------- device scratch ----------------
__device__ __half g_xh [(size_t)MTOT*DD];
__device__ __half g_Qh [(size_t)DD*DD];
__device__ __half g_Kh [(size_t)DD*DD];
__device__ __half g_Wtv[(size_t)DD*DD];     // V^T: [n][k]
__device__ __half g_Mt [(size_t)DD*DD];     // (K Q^T)
__device__ __half g_Yh [(size_t)MTOT*DD];   // y = x @ (Q K^T)
__device__ __half g_Vxh[(size_t)MTOT*DD];
__device__ __half g_Vth[(size_t)MTOT*DD];   // Vx^T: [b][d][s]
__device__ __half g_Sh [(size_t)BB*SS*SS];  // scaled logits, fp16
__device__ __half g_Ph [(size_t)BB*SS*SS];

// ---------------- asm helpers ----------------
__device__ __forceinline__ uint32_t smem_u32(const void* p){
    uint32_t a;
    asm("{ .reg .u64 t; cvta.to.shared.u64 t, %1; cvt.u32.u64 %0, t; }" : "=r"(a) : "l"(p));
    return a;
}
#define CPA(dst, src) asm volatile("cp.async.cg.shared.global [%0], [%1], 16;" :: "r"(dst), "l"(src))
#define CPC()  asm volatile("cp.async.commit_group;")

template<int N> __device__ __forceinline__ void cp_wait();
template<> __device__ __forceinline__ void cp_wait<1>(){ asm volatile("cp.async.wait_group 1;"); }
template<> __device__ __forceinline__ void cp_wait<4>(){ asm volatile("cp.async.wait_group 4;"); }

#define LDSM4(r0,r1,r2,r3,addr) \
    asm volatile("ldmatrix.sync.aligned.m8n8.x4.shared.b16 {%0,%1,%2,%3}, [%4];" \
        : "=r"(r0), "=r"(r1), "=r"(r2), "=r"(r3) : "r"(addr))

#define MMA(d, a, b) asm volatile( \
    "mma.sync.aligned.m16n8k16.row.col.f32.f16.f16.f32 " \
    "{%0,%1,%2,%3}, {%4,%5,%6,%7}, {%8,%9}, {%0,%1,%2,%3};" \
    : "+f"((d)[0]), "+f"((d)[1]), "+f"((d)[2]), "+f"((d)[3]) \
    : "r"((a)[0]), "r"((a)[1]), "r"((a)[2]), "r"((a)[3]), "r"((b)[0]), "r"((b)[1]))

__device__ __forceinline__ uint32_t swz(uint32_t r, uint32_t c){
    return r*64u + ((c ^ (r & 3u)) * 16u);
}

// ---------------- stage load (cp.async, swizzled): A, B — 128 threads -------
__device__ __forceinline__ void load_stage(uint32_t sm,
    const __half* A, size_t lda, int r0a,
    const __half* B, size_t ldb, int r0b,
    int k0, int tid)
{
#pragma unroll
    for (int i = 0; i < 4; i++){
        int id = tid + i*NTHR;                // 0..511
        uint32_t r = (uint32_t)(id >> 2), c = (uint32_t)(id & 3);
        uint32_t so = swz(r, c);
        size_t goa = (size_t)(r0a + (int)r)*lda + k0 + c*8;
        size_t gob = (size_t)(r0b + (int)r)*ldb + k0 + c*8;
        CPA(sm + so,          A + goa);
        CPA(sm + TILE_B + so, B + gob);
    }
}

// ---------------- stage compute: warp tile 64x64, 1-pass ----------------
__device__ __forceinline__ void compute_stage(uint32_t sm, int lane, int wm, int wn,
                                              float acc[4][8][4])
{
    const uint32_t aA = sm;
    const uint32_t aB = sm + TILE_B;
    const int ar = lane & 15;
    const int ac = lane >> 4;
    const int br = (lane & 7) | ((lane >> 4) << 3);
    const int bc = (lane >> 3) & 1;
#pragma unroll
    for (int ks = 0; ks < 2; ks++){
        uint32_t a[4][4], bh[8][2];
#pragma unroll
        for (int mi = 0; mi < 4; mi++){
            uint32_t r = (uint32_t)(wm*64 + mi*16 + ar);
            LDSM4(a[mi][0], a[mi][1], a[mi][2], a[mi][3], aA + swz(r, (uint32_t)(ks*2 + ac)));
        }
#pragma unroll
        for (int np = 0; np < 4; np++){
            uint32_t r = (uint32_t)(wn*64 + np*16 + br);
            LDSM4(bh[2*np][0], bh[2*np][1], bh[2*np+1][0], bh[2*np+1][1], aB + swz(r, (uint32_t)(ks*2 + bc)));
        }
#pragma unroll
        for (int mi = 0; mi < 4; mi++)
#pragma unroll
            for (int ni = 0; ni < 8; ni++)
                MMA(acc[mi][ni], a[mi], bh[ni]);
    }
}

// ---------------- GEMM mainloop (NST-stage pipeline, 1 sync/iter) ----------------
template<int NST>
__device__ __forceinline__ void gemm_run(uint32_t sm, int tid,
    const __half* A, size_t lda, int r0a,
    const __half* B, size_t ldb, int r0b,
    int ktiles, float acc[4][8][4])
{
    const int lane = tid & 31, wid = tid >> 5;
    const int wm = wid & 1, wn = wid >> 1;
    const int kend = ktiles * BK;

#pragma unroll
    for (int s = 0; s < NST - 1; s++){
        int k = min(s * BK, kend - BK);
        load_stage(sm + s*STAGE_B, A, lda, r0a, B, ldb, r0b, k, tid);
        CPC();
    }
    int buf = 0, nxt = NST - 1;
    for (int kt = 0; kt < ktiles; kt++){
        cp_wait<NST-2>();
        __syncthreads();
        {
            int k = min((kt + NST - 1) * BK, kend - BK);
            load_stage(sm + nxt*STAGE_B, A, lda, r0a, B, ldb, r0b, k, tid);
            CPC();
        }
        compute_stage(sm + buf*STAGE_B, lane, wm, wn, acc);
        buf = (buf + 1 == NST) ? 0 : buf + 1;
        nxt = (nxt + 1 == NST) ? 0 : nxt + 1;
    }
}

// ---------------- kernel 1: x -> fp16 ----------------
__global__ void k_half_x(const float* __restrict__ x){
    size_t i = ((size_t)blockIdx.x * 256 + threadIdx.x) * 4;
    float4 v = *reinterpret_cast<const float4*>(x + i);
    __half2 h01{__float2half(v.x), __float2half(v.y)};
    __half2 h23{__float2half(v.z), __float2half(v.w)};
    *reinterpret_cast<__half2*>(g_xh + i)     = h01;
    *reinterpret_cast<__half2*>(g_xh + i + 2) = h23;
}

// ---------------- kernel 2a: Q,K weights -> fp16 ----------------
__global__ void k_half_w(const float* __restrict__ Wq,
                         const float* __restrict__ Wk){
    const float* W = blockIdx.y ? Wk : Wq;
    __half* H      = blockIdx.y ? g_Kh : g_Qh;
    size_t i = ((size_t)blockIdx.x * 256 + threadIdx.x) * 4;
    float4 v = *reinterpret_cast<const float4*>(W + i);
    __half2 h01{__float2half(v.x), __float2half(v.y)};
    __half2 h23{__float2half(v.z), __float2half(v.w)};
    *reinterpret_cast<__half2*>(H + i)     = h01;
    *reinterpret_cast<__half2*>(H + i + 2) = h23;
}

// ---------------- kernel 2b: transpose V -> fp16 ----------------
__global__ void k_wtrans(const float* __restrict__ Wv){
    __shared__ float t[32][33];
    int tx = threadIdx.x, ty = threadIdx.y;
    int kb = blockIdx.y * 32, nb = blockIdx.x * 32;
#pragma unroll
    for (int j = 0; j < 4; j++)
        t[ty + j*8][tx] = Wv[(size_t)(kb + ty + j*8)*DD + nb + tx];
    __syncthreads();
#pragma unroll
    for (int j = 0; j < 4; j++){
        int n = nb + ty + j*8, k = kb + tx;
        g_Wtv[(size_t)n*DD + k] = __float2half(t[tx][ty + j*8]);
    }
}

// ---------------- kernel 3: Mt = K @ Q^T ----------------
__global__ void __launch_bounds__(NTHR, 1) k_M(){
    extern __shared__ __align__(128) char smem[];
    uint32_t sm = smem_u32(smem);
    const int tid = threadIdx.x;
    const int m0 = blockIdx.y*BM, n0 = blockIdx.x*BN;
    float acc[4][8][4] = {};
    gemm_run<6>(sm, tid, g_Kh, DD, m0, g_Qh, DD, n0, DD/BK, acc);
    const int lane = tid & 31, wid = tid >> 5, wm = wid & 1, wn = wid >> 1;
    const int r = lane >> 2, c = (lane & 3) * 2;
#pragma unroll
    for (int mi = 0; mi < 4; mi++)
#pragma unroll
        for (int ni = 0; ni < 8; ni++){
            int row = m0 + wm*64 + mi*16 + r;
            int col = n0 + wn*64 + ni*8 + c;
#pragma unroll
            for (int hrow = 0; hrow < 2; hrow++){
                __half2 hp{__float2half(acc[mi][ni][hrow*2+0]),
                           __float2half(acc[mi][ni][hrow*2+1])};
                *reinterpret_cast<__half2*>(g_Mt + (size_t)(row + hrow*8)*DD + col) = hp;
            }
        }
}

// ---------------- kernel 4: V projection -> fp16 ----------------
__global__ void __launch_bounds__(NTHR, 2) k_proj_v(){
    extern __shared__ __align__(128) char smem[];
    uint32_t sm = smem_u32(smem);
    const int tid = threadIdx.x;
    const int m0 = blockIdx.y*BM, n0 = blockIdx.x*BN;
    float acc[4][8][4] = {};
    gemm_run<3>(sm, tid, g_xh, DD, m0, g_Wtv, DD, n0, DD/BK, acc);
    const int lane = tid & 31, wid = tid >> 5, wm = wid & 1, wn = wid >> 1;
    const int r = lane >> 2, c = (lane & 3) * 2;
#pragma unroll
    for (int mi = 0; mi < 4; mi++)
#pragma unroll
        for (int ni = 0; ni < 8; ni++){
            int row = m0 + wm*64 + mi*16 + r;
            int col = n0 + wn*64 + ni*8 + c;
#pragma unroll
            for (int hrow = 0; hrow < 2; hrow++){
                size_t o = (size_t)(row + hrow*8)*DD + col;
                __half2 hp{__float2half(acc[mi][ni][hrow*2+0]),
                           __float2half(acc[mi][ni][hrow*2+1])};
                *reinterpret_cast<__half2*>(g_Vxh + o) = hp;
            }
        }
}

// ---------------- kernel 5: y = x @ M ----------------
__global__ void __launch_bounds__(NTHR, 2) k_y(){
    extern __shared__ __align__(128) char smem[];
    uint32_t sm = smem_u32(smem);
    const int tid = threadIdx.x;
    const int m0 = blockIdx.y*BM, n0 = blockIdx.x*BN;
    float acc[4][8][4] = {};
    gemm_run<3>(sm, tid, g_xh, DD, m0, g_Mt, DD, n0, DD/BK, acc);
    const int lane = tid & 31, wid = tid >> 5, wm = wid & 1, wn = wid >> 1;
    const int r = lane >> 2, c = (lane & 3) * 2;
#pragma unroll
    for (int mi = 0; mi < 4; mi++)
#pragma unroll
        for (int ni = 0; ni < 8; ni++){
            int row = m0 + wm*64 + mi*16 + r;
            int col = n0 + wn*64 + ni*8 + c;
#pragma unroll
            for (int hrow = 0; hrow < 2; hrow++){
                __half2 hp{__float2half(acc[mi][ni][hrow*2+0]),
                           __float2half(acc[mi][ni][hrow*2+1])};
                *reinterpret_cast<__half2*>(g_Yh + (size_t)(row + hrow*8)*DD + col) = hp;
            }
        }
}

// ---------------- kernel 6: transpose Vx ----------------
__global__ void k_vtrans(){
    const int b = blockIdx.z;
    const __half* Vx = g_Vxh + (size_t)b*SS*DD;
    __half* H = g_Vth + (size_t)b*DD*SS;
    __shared__ float t[32][33];
    int tx = threadIdx.x, ty = threadIdx.y;
    int s0 = blockIdx.y * 32, d0 = blockIdx.x * 32;
#pragma unroll
    for (int j = 0; j < 4; j++)
        t[ty + j*8][tx] = __half2float(Vx[(size_t)(s0 + ty + j*8)*DD + d0 + tx]);
    __syncthreads();
#pragma unroll
    for (int j = 0; j < 4; j++){
        int d = d0 + ty + j*8, s = s0 + tx;
        H[(size_t)d*SS + s] = __float2half(t[tx][ty + j*8]);
    }
}

// ---------------- kernel 7: scores = y @ x^T (lower-tri, fp16 out) ----------
__global__ void __launch_bounds__(NTHR, 2) k_scores(){
    const int kt = blockIdx.x, qt = blockIdx.y, b = blockIdx.z;
    if (kt > qt) return;
    extern __shared__ __align__(128) char smem[];
    uint32_t sm = smem_u32(smem);
    const int tid = threadIdx.x;
    float acc[4][8][4] = {};
    gemm_run<3>(sm, tid,
                g_Yh + (size_t)b*SS*DD, DD, qt*BM,
                g_xh + (size_t)b*SS*DD, DD, kt*BN, DD/BK, acc);
    const int lane = tid & 31, wid = tid >> 5, wm = wid & 1, wn = wid >> 1;
    const int r = lane >> 2, c = (lane & 3) * 2;
    __half* Sp = g_Sh + (size_t)b*SS*SS;
#pragma unroll
    for (int mi = 0; mi < 4; mi++)
#pragma unroll
        for (int ni = 0; ni < 8; ni++){
            int row = qt*BM + wm*64 + mi*16 + r;
            int col = kt*BN + wn*64 + ni*8 + c;
#pragma unroll
            for (int hrow = 0; hrow < 2; hrow++){
                size_t o = (size_t)(row + hrow*8)*SS + col;
                __half2 hp{__float2half(acc[mi][ni][hrow*2+0]*0.03125f),
                           __float2half(acc[mi][ni][hrow*2+1]*0.03125f)};
                *reinterpret_cast<__half2*>(Sp + o) = hp;
            }
        }
}

// ---------------- kernel 8: softmax (fp16 in) -> fp16 probs + pad ----------
__global__ void k_softmax(){
    const int q = blockIdx.x;
    const int b = blockIdx.y;
    const __half* row = g_Sh + (size_t)b*SS*SS + (size_t)q*SS;
    __half* Ph = g_Ph + (size_t)b*SS*SS + (size_t)q*SS;
    const int len = q + 1;

    __shared__ float buf[SS];
    __shared__ float red[256];
    const int tid = threadIdx.x;

    float mx = -1e30f;
    for (int i = tid; i < len; i += 256){
        float v = __half2float(row[i]);
        buf[i] = v;
        mx = fmaxf(mx, v);
    }
    red[tid] = mx;
    __syncthreads();
    for (int s = 128; s > 0; s >>= 1){
        if (tid < s) red[tid] = fmaxf(red[tid], red[tid + s]);
        __syncthreads();
    }
    mx = red[0];
    __syncthreads();

    float sum = 0.f;
    for (int i = tid; i < len; i += 256){
        float e = __expf(buf[i] - mx);
        buf[i] = e;
        sum += e;
    }
    red[tid] = sum;
    __syncthreads();
    for (int s = 128; s > 0; s >>= 1){
        if (tid < s) red[tid] += red[tid + s];
        __syncthreads();
    }
    const float inv = 1.0f / red[0];
    __syncthreads();

    for (int i = tid; i < len; i += 256)
        Ph[i] = __float2half(buf[i] * inv);
    const int bound = ((q >> 7) + 1) << 7;
    const __half z = __float2half(0.f);
    for (int i = len + tid; i < bound; i += 256) Ph[i] = z;
}

// ---------------- kernel 9: O = P @ V (triangular; longest-first) ----------
__global__ void __launch_bounds__(NTHR, 2) k_pv(float* __restrict__ Out){
    const int dt = blockIdx.x, b = blockIdx.z;
    const int qt = (int)gridDim.y - 1 - (int)blockIdx.y;   // longest first
    extern __shared__ __align__(128) char smem[];
    uint32_t sm = smem_u32(smem);
    const int tid = threadIdx.x;
    float acc[4][8][4] = {};
    const int ktiles = (qt + 1) * (BM / BK);
    gemm_run<3>(sm, tid,
                g_Ph  + (size_t)b*SS*SS, SS, qt*BM,
                g_Vth + (size_t)b*DD*SS, SS, dt*BN, ktiles, acc);
    const int lane = tid & 31, wid = tid >> 5, wm = wid & 1, wn = wid >> 1;
    const int r = lane >> 2, c = (lane & 3) * 2;
#pragma unroll
    for (int mi = 0; mi < 4; mi++)
#pragma unroll
        for (int ni = 0; ni < 8; ni++){
            int row = qt*BM + wm*64 + mi*16 + r;
            int col = dt*BN + wn*64 + ni*8 + c;
#pragma unroll
            for (int hrow = 0; hrow < 2; hrow++){
                size_t o = ((size_t)b*SS + row + hrow*8)*DD + col;
                *reinterpret_cast<float2*>(Out + o) =
                    make_float2(acc[mi][ni][hrow*2+0], acc[mi][ni][hrow*2+1]);
            }
        }
}

// ---------------- host ----------------
extern "C" void kernel_launch(void* const* d_in, const int* in_sizes, int n_in,
                              void* d_out, int out_size) {
    const float* x  = (const float*)d_in[0];
    const float* Q  = (const float*)d_in[1];
    const float* K  = (const float*)d_in[2];
    const float* V  = (const float*)d_in[3];
    float* out = (float*)d_out;

    cudaFuncSetAttribute(k_M,      cudaFuncAttributeMaxDynamicSharedMemorySize, SMEM_BYTES6);
    cudaFuncSetAttribute(k_proj_v, cudaFuncAttributeMaxDynamicSharedMemorySize, SMEM_BYTES);
    cudaFuncSetAttribute(k_y,      cudaFuncAttributeMaxDynamicSharedMemorySize, SMEM_BYTES);
    cudaFuncSetAttribute(k_scores, cudaFuncAttributeMaxDynamicSharedMemorySize, SMEM_BYTES);
    cudaFuncSetAttribute(k_pv,     cudaFuncAttributeMaxDynamicSharedMemorySize, SMEM_BYTES);

    // Second stream for the weight / V chain (capture-legal fork via events).
    cudaStream_t s1;
    cudaStreamCreateWithFlags(&s1, cudaStreamNonBlocking);
    cudaEvent_t e_fork, e_x, e_M, e_vt;
    cudaEventCreateWithFlags(&e_fork, cudaEventDisableTiming);
    cudaEventCreateWithFlags(&e_x,    cudaEventDisableTiming);
    cudaEventCreateWithFlags(&e_M,    cudaEventDisableTiming);
    cudaEventCreateWithFlags(&e_vt,   cudaEventDisableTiming);

    // fork s1 off the main (capturing) stream
    cudaEventRecord(e_fork, 0);
    cudaStreamWaitEvent(s1, e_fork, 0);

    // main stream: x conversion (critical path)
    k_half_x<<<(unsigned)((size_t)MTOT*DD/1024), 256>>>(x);
    cudaEventRecord(e_x, 0);

    // s1: weight chain (independent of x until proj_v)
    k_half_w<<<dim3(DD*DD/1024, 2), 256, 0, s1>>>(Q, K);
    k_wtrans<<<dim3(DD/32, DD/32), dim3(32, 8), 0, s1>>>(V);
    k_M<<<dim3(DD/BN, DD/BM), NTHR, SMEM_BYTES6, s1>>>();
    cudaEventRecord(e_M, s1);
    cudaStreamWaitEvent(s1, e_x, 0);          // proj_v needs g_xh
    k_proj_v<<<dim3(DD/BN, MTOT/BM), NTHR, SMEM_BYTES, s1>>>();
    k_vtrans<<<dim3(DD/32, SS/32, BB), dim3(32, 8), 0, s1>>>();
    cudaEventRecord(e_vt, s1);

    // main stream: y -> scores -> softmax (overlaps proj_v/vtrans on s1)
    cudaStreamWaitEvent(0, e_M, 0);           // y needs g_Mt
    k_y<<<dim3(DD/BN, MTOT/BM), NTHR, SMEM_BYTES>>>();
    k_scores<<<dim3(SS/BN, SS/BM, BB), NTHR, SMEM_BYTES>>>();
    k_softmax<<<dim3(SS, BB), 256>>>();

    // join: pv needs softmax (stream 0) + vtrans (s1)
    cudaStreamWaitEvent(0, e_vt, 0);
    k_pv<<<dim3(DD/BN, SS/BM, BB), NTHR, SMEM_BYTES>>>(out);
}